// round 4
// baseline (speedup 1.0000x reference)
#include <cuda_runtime.h>
#include <math.h>

#define NN 6000
#define EE 100000
#define NB 148          // persistent-kernel block count (co-resident on 148+ SMs)

typedef unsigned long long ull;

// ---------------- f32x2 packed-FMA helpers (sm_103a FFMA2) ----------------------
__device__ __forceinline__ void fma2(ull& d, ull a, ull b) {
    asm("fma.rn.f32x2 %0, %1, %2, %0;" : "+l"(d) : "l"(a), "l"(b));
}
__device__ __forceinline__ ull pack2(float lo, float hi) {
    ull r; asm("mov.b64 %0, {%1, %2};" : "=l"(r) : "f"(lo), "f"(hi)); return r;
}
__device__ __forceinline__ float2 unpack2(ull v) {
    float2 r; asm("mov.b64 {%0, %1}, %2;" : "=f"(r.x), "=f"(r.y) : "l"(v)); return r;
}

// ---------------- scratch (device globals; no allocations allowed) -------------
__device__ float g_W0[2 * NN * 32];    // layer-0 combined basis (x=I shortcut)
__device__ float g_Ha[2 * NN * 64];    // H double buffer A
__device__ float g_Hb[2 * NN * 64];    // H double buffer B
__device__ float g_baseA[NN * 64];
__device__ float g_baseB[NN * 64];
__device__ float g_Wr1[2 * 32 * 64];
__device__ float g_Wr2[2 * 64 * 64];
__device__ float g_Wr3[2 * 64 * 32];
__device__ float g_h[NN * 512];        // GAT projected features
__device__ float g_xg[NN * 512];       // GAT output
__device__ float g_ab[NN * 256];       // [A | B] for edge MLP
__device__ float g_asv[NN];
__device__ float g_adv[NN];
__device__ float g_ps[32];
__device__ float g_pd[32];
__device__ int   g_deg[NN];
__device__ int   g_rowptr[NN + 1];
__device__ int   g_cursor[NN];
__device__ int   g_cpack[EE];          // src | (type<<31)
__device__ int   g_bar_count;
__device__ int   g_bar_gen;

// ---------------- software grid barrier (all NB blocks co-resident) -------------
__device__ __forceinline__ void grid_barrier() {
    __syncthreads();
    if (threadIdx.x == 0) {
        int gen = atomicAdd(&g_bar_gen, 0);
        __threadfence();
        if (atomicAdd(&g_bar_count, 1) == NB - 1) {
            g_bar_count = 0;
            __threadfence();
            atomicAdd(&g_bar_gen, 1);
        } else {
            while (atomicAdd(&g_bar_gen, 0) == gen) __nanosleep(64);
        }
    }
    __syncthreads();
}

// ---------------- persistent: prep + count + scan + fill ------------------------
// prep segments (each 256-aligned):
//   [0, 384000)        W0
//   [+4096)            Wr1
//   [+8192)            Wr2
//   [+4096)            Wr3
//   [+6144)            zero deg (first 6000)
//   [+2048)            ps/pd (64 warp-dots)
#define SEG_W0   384000
#define SEG_WR1  (SEG_W0 + 4096)
#define SEG_WR2  (SEG_WR1 + 8192)
#define SEG_WR3  (SEG_WR2 + 4096)
#define SEG_DEG  (SEG_WR3 + 6144)
#define SEG_PSPD (SEG_DEG + 2048)

__global__ __launch_bounds__(256) void csr_prep_kernel(
    const float* __restrict__ basis0, const float* __restrict__ comp0,
    const float* __restrict__ basis1, const float* __restrict__ comp1,
    const float* __restrict__ basis2, const float* __restrict__ comp2,
    const float* __restrict__ basis3, const float* __restrict__ comp3,
    const float* __restrict__ gw, const float* __restrict__ a_s,
    const float* __restrict__ a_d,
    const int* __restrict__ ei, const int* __restrict__ et,
    float* __restrict__ W0, float* __restrict__ Wr1,
    float* __restrict__ Wr2, float* __restrict__ Wr3,
    int* __restrict__ deg, int* __restrict__ rowptr, int* __restrict__ cursor,
    int* __restrict__ cpack, float* __restrict__ ps, float* __restrict__ pd) {
    const int tid = threadIdx.x;
    const int gtid = blockIdx.x * 256 + tid;
    const int gstride = NB * 256;

    // ---- phase 0: prep ----
    for (int idx = gtid; idx < SEG_PSPD; idx += gstride) {
        int i = idx;
        if (i < SEG_W0) {
            int r = i / 192000, io = i - r * 192000;
            float s = 0.f;
#pragma unroll
            for (int b = 0; b < 4; b++) s += comp0[r * 4 + b] * basis0[b * 192000 + io];
            W0[i] = s;
        } else if (i < SEG_WR1) {
            i -= SEG_W0;
            int r = i / 2048, io = i - r * 2048;
            float s = 0.f;
#pragma unroll
            for (int b = 0; b < 4; b++) s += comp1[r * 4 + b] * basis1[b * 2048 + io];
            Wr1[i] = s;
        } else if (i < SEG_WR2) {
            i -= SEG_WR1;
            int r = i / 4096, io = i - r * 4096;
            float s = 0.f;
#pragma unroll
            for (int b = 0; b < 4; b++) s += comp2[r * 4 + b] * basis2[b * 4096 + io];
            Wr2[i] = s;
        } else if (i < SEG_WR3) {
            i -= SEG_WR2;
            int r = i / 2048, io = i - r * 2048;
            float s = 0.f;
#pragma unroll
            for (int b = 0; b < 4; b++) s += comp3[r * 4 + b] * basis3[b * 2048 + io];
            Wr3[i] = s;
        } else if (i < SEG_DEG) {
            i -= SEG_WR3;
            if (i < NN) deg[i] = 0;
        } else {
            i -= SEG_DEG;
            int w = i >> 5, lane = i & 31;
            int row = w & 31;
            const float* a = (w < 32) ? a_s : a_d;
            float s = 0.f;
            for (int c = lane; c < 512; c += 32) s += gw[row * 512 + c] * a[c];
#pragma unroll
            for (int off = 16; off > 0; off >>= 1) s += __shfl_down_sync(0xffffffffu, s, off);
            if (lane == 0) { if (w < 32) ps[row] = s; else pd[row] = s; }
        }
    }
    grid_barrier();

    // ---- phase 1: count in-degrees ----
    for (int e = gtid; e < EE; e += gstride) atomicAdd(&deg[ei[EE + e]], 1);
    grid_barrier();

    // ---- phase 2: exclusive scan (block 0 only; 256 thr x 24 elems) ----
    if (blockIdx.x == 0) {
        int base = tid * 24;
        int loc[24];
        int sum = 0;
#pragma unroll
        for (int i = 0; i < 24; i++) {
            int idx = base + i;
            int v = (idx < NN) ? deg[idx] : 0;
            loc[i] = sum;
            sum += v;
        }
        int lane = tid & 31, w = tid >> 5;
        int v = sum;
#pragma unroll
        for (int off = 1; off < 32; off <<= 1) {
            int n = __shfl_up_sync(0xffffffffu, v, off);
            if (lane >= off) v += n;
        }
        __shared__ int wsum[8];
        __shared__ int stotal;
        if (lane == 31) wsum[w] = v;
        __syncthreads();
        if (tid == 0) {
            int run = 0;
#pragma unroll
            for (int j = 0; j < 8; j++) { int t = wsum[j]; wsum[j] = run; run += t; }
            stotal = run;
        }
        __syncthreads();
        int incl = v + wsum[w];
        int excl = incl - sum;
#pragma unroll
        for (int i = 0; i < 24; i++) {
            int idx = base + i;
            if (idx < NN) { rowptr[idx] = excl + loc[i]; cursor[idx] = excl + loc[i]; }
        }
        if (tid == 0) rowptr[NN] = stotal;
    }
    grid_barrier();

    // ---- phase 3: fill (packed src|type<<31) ----
    for (int e = gtid; e < EE; e += gstride) {
        int s = ei[e];
        int d = ei[EE + e];
        int t = et[e];
        int pos = atomicAdd(&cursor[d], 1);
        cpack[pos] = s | (t << 31);
    }
}

// ---------------- fused agg(L) + dense(L+1) ------------------------------------
// Block: 256 threads, M=16 nodes. Phase1 aggregates layer-L output for the
// block's own nodes into shared (tanh applied); Phase2 runs the next layer's
// dense GEMM out of shared with f32x2 node-pair accumulators.
template<int IN, int OUT>
__global__ __launch_bounds__(256) void fused_agg_dense(
    const float* __restrict__ Hin, const float* __restrict__ basein,
    const float* __restrict__ bias,
    const int* __restrict__ rowptr, const int* __restrict__ cpack,
    const float* __restrict__ Wr, const float* __restrict__ root,
    float* __restrict__ Hout, float* __restrict__ baseout) {
    constexpr int M = 16;
    __shared__ float xsT[IN][M];
    __shared__ float wsh[2 * IN * OUT];
    const int tid = threadIdx.x;
    const int n0 = blockIdx.x * M;

    for (int i = tid; i < 2 * IN * OUT; i += 256) wsh[i] = Wr[i];

    // phase 1: aggregate + tanh into shared (transposed)
    {
        const int k = tid % IN;
        const int mr = tid / IN;
        constexpr int NP = 256 / IN;
        for (int m = mr; m < M; m += NP) {
            int n = n0 + m;
            int e0 = rowptr[n], e1 = rowptr[n + 1];
            float a0 = 0.f, a1 = 0.f;
            int c0 = 0, c1 = 0;
            for (int e = e0; e < e1; e++) {
                int p = cpack[e];
                int s = p & 0x7fffffff;
                int rel = ((unsigned)p) >> 31;
                float v = Hin[(rel * NN + s) * IN + k];
                if (rel) { a1 += v; c1++; } else { a0 += v; c0++; }
            }
            xsT[k][m] = tanhf(basein[n * IN + k] + bias[k]
                              + a0 / fmaxf((float)c0, 1.f) + a1 / fmaxf((float)c1, 1.f));
        }
    }
    __syncthreads();

    // phase 2: dense GEMM for next layer
    constexpr int G = 256 / OUT;
    constexpr int P = (M / 2) / G;
    const int o = tid & (OUT - 1);
    const int g = tid / OUT;
    ull a0[P], a1[P], ar[P];
#pragma unroll
    for (int p = 0; p < P; p++) { a0[p] = 0; a1[p] = 0; ar[p] = 0; }
    for (int i = 0; i < IN; i++) {
        float w0 = wsh[i * OUT + o];
        float w1 = wsh[IN * OUT + i * OUT + o];
        float wr = __ldg(&root[i * OUT + o]);
        ull w0d = pack2(w0, w0), w1d = pack2(w1, w1), wrd = pack2(wr, wr);
#pragma unroll
        for (int p = 0; p < P; p++) {
            ull xp = *(const ull*)&xsT[i][2 * (g * P + p)];
            fma2(a0[p], xp, w0d);
            fma2(a1[p], xp, w1d);
            fma2(ar[p], xp, wrd);
        }
    }
#pragma unroll
    for (int p = 0; p < P; p++) {
        int n = n0 + 2 * (g * P + p);
        float2 v0 = unpack2(a0[p]), v1 = unpack2(a1[p]), vr = unpack2(ar[p]);
        Hout[n * OUT + o] = v0.x;        Hout[(n + 1) * OUT + o] = v0.y;
        Hout[(NN + n) * OUT + o] = v1.x; Hout[(NN + n + 1) * OUT + o] = v1.y;
        baseout[n * OUT + o] = vr.x;     baseout[(n + 1) * OUT + o] = vr.y;
    }
}

// ---------------- fused agg(L3) + GAT projection --------------------------------
__device__ __forceinline__ float lrelu02(float a) { return a > 0.f ? a : 0.2f * a; }

__global__ __launch_bounds__(512) void gat_h_fused(
    const float* __restrict__ Hin, const float* __restrict__ basein,
    const float* __restrict__ bias,
    const int* __restrict__ rowptr, const int* __restrict__ cpack,
    const float* __restrict__ gw, const float* __restrict__ ps,
    const float* __restrict__ pd,
    float* __restrict__ h, float* __restrict__ asv, float* __restrict__ adv) {
    __shared__ float xsT[32][40];
    const int c = threadIdx.x;
    const int n0 = blockIdx.x * 40;

    // phase 1: aggregate layer-3 output for the 40 nodes into shared
    {
        const int k = c & 31;
        const int mr = c >> 5;  // 16 node rows per pass
        for (int m = mr; m < 40; m += 16) {
            int n = n0 + m;
            int e0 = rowptr[n], e1 = rowptr[n + 1];
            float a0 = 0.f, a1 = 0.f;
            int c0 = 0, c1 = 0;
            for (int e = e0; e < e1; e++) {
                int p = cpack[e];
                int s = p & 0x7fffffff;
                int rel = ((unsigned)p) >> 31;
                float v = Hin[(rel * NN + s) * 32 + k];
                if (rel) { a1 += v; c1++; } else { a0 += v; c0++; }
            }
            xsT[k][m] = tanhf(basein[n * 32 + k] + bias[k]
                              + a0 / fmaxf((float)c0, 1.f) + a1 / fmaxf((float)c1, 1.f));
        }
    }
    __syncthreads();

    // phase 2: h = x @ gw (gw column cached in registers, f32x2 node pairs)
    ull gwd[32];
#pragma unroll
    for (int k = 0; k < 32; k++) {
        float g = gw[k * 512 + c];
        gwd[k] = pack2(g, g);
    }
#pragma unroll 4
    for (int mp = 0; mp < 20; mp++) {
        ull acc = 0;
#pragma unroll
        for (int k = 0; k < 32; k++) {
            ull xp = *(const ull*)&xsT[k][2 * mp];
            fma2(acc, xp, gwd[k]);
        }
        float2 v = unpack2(acc);
        h[(size_t)(n0 + 2 * mp) * 512 + c] = v.x;
        h[(size_t)(n0 + 2 * mp + 1) * 512 + c] = v.y;
    }
    if (c < 40) {
        float s = 0.f, t = 0.f;
#pragma unroll
        for (int k = 0; k < 32; k++) {
            float xv = xsT[k][c];
            s += xv * __ldg(&ps[k]);
            t += xv * __ldg(&pd[k]);
        }
        asv[n0 + c] = s;
        adv[n0 + c] = t;
    }
}

// ---------------- GAT aggregation (softmax + weighted sum) ----------------------
__global__ void gat_agg_kernel(const float* __restrict__ h, const float* __restrict__ asv,
                               const float* __restrict__ adv,
                               const int* __restrict__ rowptr, const int* __restrict__ cpack,
                               const float* __restrict__ gbias, float* __restrict__ xout) {
    int n = blockIdx.x;
    int t = threadIdx.x;  // 128 threads, float4 per thread
    int e0 = rowptr[n], e1 = rowptr[n + 1];
    float advn = adv[n];
    float aself = lrelu02(asv[n] + advn);
    float lm = aself;
    for (int e = e0 + t; e < e1; e += 128)
        lm = fmaxf(lm, lrelu02(asv[cpack[e] & 0x7fffffff] + advn));
    __shared__ float sred[128];
    sred[t] = lm;
    __syncthreads();
    for (int off = 64; off > 0; off >>= 1) {
        if (t < off) sred[t] = fmaxf(sred[t], sred[t + off]);
        __syncthreads();
    }
    float m = sred[0];
    __shared__ float sEx[128];
    __shared__ int sSrc[128];
    float4 acc = make_float4(0.f, 0.f, 0.f, 0.f);
    float denom = 0.f;
    for (int eb = e0; eb < e1; eb += 128) {
        int cnt = min(128, e1 - eb);
        __syncthreads();
        if (t < cnt) {
            int s = cpack[eb + t] & 0x7fffffff;
            sSrc[t] = s;
            sEx[t] = expf(lrelu02(asv[s] + advn) - m);
        }
        __syncthreads();
        for (int j = 0; j < cnt; j++) {
            float ex = sEx[j];
            const float4* hr = reinterpret_cast<const float4*>(h + (size_t)sSrc[j] * 512);
            float4 v = hr[t];
            acc.x += ex * v.x; acc.y += ex * v.y; acc.z += ex * v.z; acc.w += ex * v.w;
            denom += ex;
        }
    }
    float exs = expf(aself - m);
    denom += exs;
    {
        const float4* hn = reinterpret_cast<const float4*>(h + (size_t)n * 512);
        float4 v = hn[t];
        acc.x += exs * v.x; acc.y += exs * v.y; acc.z += exs * v.z; acc.w += exs * v.w;
    }
    float inv = 1.f / fmaxf(denom, 1e-16f);
    float4 g = reinterpret_cast<const float4*>(gbias)[t];
    float4 o;
    o.x = fmaxf(acc.x * inv + g.x, 0.f);
    o.y = fmaxf(acc.y * inv + g.y, 0.f);
    o.z = fmaxf(acc.z * inv + g.z, 0.f);
    o.w = fmaxf(acc.w * inv + g.w, 0.f);
    reinterpret_cast<float4*>(xout + (size_t)n * 512)[t] = o;
}

// ---------------- edge MLP ------------------------------------------------------
__global__ __launch_bounds__(256) void gemm_ab_kernel(const float* __restrict__ xg,
                                                      const float* __restrict__ w1,
                                                      float* __restrict__ ab) {
    __shared__ float xsT[32][40];
    __shared__ float ws[32][256];
    const int c = threadIdx.x;
    const int n0 = blockIdx.x * 40;
    ull acc[20];
#pragma unroll
    for (int p = 0; p < 20; p++) acc[p] = 0;
    for (int k0 = 0; k0 < 512; k0 += 32) {
        __syncthreads();
        for (int i = c; i < 40 * 32; i += 256) {
            int m = i >> 5, kk = i & 31;
            xsT[kk][m] = xg[(size_t)(n0 + m) * 512 + k0 + kk];
        }
        for (int i = c; i < 32 * 256; i += 256) {
            int kk = i >> 8, cc = i & 255;
            int krow = k0 + kk + ((cc < 128) ? 0 : 512);
            int col = cc & 127;
            ws[kk][cc] = w1[krow * 128 + col];
        }
        __syncthreads();
#pragma unroll 8
        for (int kk = 0; kk < 32; kk++) {
            float wv = ws[kk][c];
            ull wd = pack2(wv, wv);
            const float* xr = &xsT[kk][0];
#pragma unroll
            for (int p = 0; p < 20; p++) {
                ull xp = *(const ull*)(xr + 2 * p);
                fma2(acc[p], xp, wd);
            }
        }
    }
#pragma unroll
    for (int p = 0; p < 20; p++) {
        float2 v = unpack2(acc[p]);
        ab[(size_t)(n0 + 2 * p) * 256 + c] = v.x;
        ab[(size_t)(n0 + 2 * p + 1) * 256 + c] = v.y;
    }
}

__global__ void edge_kernel(const int* __restrict__ ei, const float* __restrict__ ab,
                            const float* __restrict__ b1, const float* __restrict__ w2,
                            const float* __restrict__ b2, float* __restrict__ out) {
    int gid = blockIdx.x * blockDim.x + threadIdx.x;
    int e = gid >> 5;
    int lane = gid & 31;
    if (e >= EE) return;
    int s = ei[e];
    int d = ei[EE + e];
    float4 a = reinterpret_cast<const float4*>(ab + (size_t)s * 256)[lane];
    float4 bv = reinterpret_cast<const float4*>(ab + (size_t)d * 256 + 128)[lane];
    float4 bb = reinterpret_cast<const float4*>(b1)[lane];
    float4 wv = reinterpret_cast<const float4*>(w2)[lane];
    float acc = fmaxf(a.x + bv.x + bb.x, 0.f) * wv.x
              + fmaxf(a.y + bv.y + bb.y, 0.f) * wv.y
              + fmaxf(a.z + bv.z + bb.z, 0.f) * wv.z
              + fmaxf(a.w + bv.w + bb.w, 0.f) * wv.w;
#pragma unroll
    for (int off = 16; off > 0; off >>= 1) acc += __shfl_down_sync(0xffffffffu, acc, off);
    if (lane == 0) out[e] = 1.f / (1.f + expf(-(acc + b2[0])));
}

// ---------------- launch ---------------------------------------------------------
extern "C" void kernel_launch(void* const* d_in, const int* in_sizes, int n_in,
                              void* d_out, int out_size) {
    const float *basis[4], *comp[4], *root[4], *rbias[4];
    const float *gat_w, *att_s, *att_d, *gat_b, *w1, *b1, *w2, *b2;
    const int *ei, *et;

    if (in_sizes[0] == 2 * EE) {
        ei = (const int*)d_in[0];
        et = (const int*)d_in[1];
        int k = 2;
        for (int l = 0; l < 4; l++) {
            basis[l] = (const float*)d_in[k++];
            comp[l]  = (const float*)d_in[k++];
            root[l]  = (const float*)d_in[k++];
            rbias[l] = (const float*)d_in[k++];
        }
        gat_w = (const float*)d_in[18]; att_s = (const float*)d_in[19];
        att_d = (const float*)d_in[20]; gat_b = (const float*)d_in[21];
        w1 = (const float*)d_in[22]; b1 = (const float*)d_in[23];
        w2 = (const float*)d_in[24]; b2 = (const float*)d_in[25];
    } else if (in_sizes[0] == 4 * NN * 32) {
        int k = 0;
        for (int l = 0; l < 4; l++) {
            basis[l] = (const float*)d_in[k++];
            comp[l]  = (const float*)d_in[k++];
            root[l]  = (const float*)d_in[k++];
            rbias[l] = (const float*)d_in[k++];
        }
        gat_w = (const float*)d_in[16]; att_s = (const float*)d_in[17];
        att_d = (const float*)d_in[18]; gat_b = (const float*)d_in[19];
        w1 = (const float*)d_in[20]; b1 = (const float*)d_in[21];
        w2 = (const float*)d_in[22]; b2 = (const float*)d_in[23];
        ei = (const int*)d_in[24]; et = (const int*)d_in[25];
    } else {
        b1 = (const float*)d_in[0]; b2 = (const float*)d_in[1];
        for (int l = 0; l < 4; l++) basis[l] = (const float*)d_in[2 + l];
        for (int l = 0; l < 4; l++) comp[l] = (const float*)d_in[6 + l];
        ei = (const int*)d_in[10]; et = (const int*)d_in[11];
        att_d = (const float*)d_in[12]; att_s = (const float*)d_in[13];
        gat_b = (const float*)d_in[14]; gat_w = (const float*)d_in[15];
        for (int l = 0; l < 4; l++) rbias[l] = (const float*)d_in[16 + l];
        for (int l = 0; l < 4; l++) root[l] = (const float*)d_in[20 + l];
        w1 = (const float*)d_in[24]; w2 = (const float*)d_in[25];
    }

    float *W0, *Ha, *Hb, *baseA, *baseB, *Wr1, *Wr2, *Wr3, *h, *xg, *ab, *asv, *adv, *ps, *pd;
    int *deg, *rowptr, *cursor, *cpack;
    cudaGetSymbolAddress((void**)&W0, g_W0);
    cudaGetSymbolAddress((void**)&Ha, g_Ha);
    cudaGetSymbolAddress((void**)&Hb, g_Hb);
    cudaGetSymbolAddress((void**)&baseA, g_baseA);
    cudaGetSymbolAddress((void**)&baseB, g_baseB);
    cudaGetSymbolAddress((void**)&Wr1, g_Wr1);
    cudaGetSymbolAddress((void**)&Wr2, g_Wr2);
    cudaGetSymbolAddress((void**)&Wr3, g_Wr3);
    cudaGetSymbolAddress((void**)&h, g_h);
    cudaGetSymbolAddress((void**)&xg, g_xg);
    cudaGetSymbolAddress((void**)&ab, g_ab);
    cudaGetSymbolAddress((void**)&asv, g_asv);
    cudaGetSymbolAddress((void**)&adv, g_adv);
    cudaGetSymbolAddress((void**)&ps, g_ps);
    cudaGetSymbolAddress((void**)&pd, g_pd);
    cudaGetSymbolAddress((void**)&deg, g_deg);
    cudaGetSymbolAddress((void**)&rowptr, g_rowptr);
    cudaGetSymbolAddress((void**)&cursor, g_cursor);
    cudaGetSymbolAddress((void**)&cpack, g_cpack);

    float* out = (float*)d_out;

    // 1) persistent prep + CSR build (software grid barriers, co-resident)
    csr_prep_kernel<<<NB, 256>>>(
        basis[0], comp[0], basis[1], comp[1], basis[2], comp[2], basis[3], comp[3],
        gat_w, att_s, att_d, ei, et,
        W0, Wr1, Wr2, Wr3, deg, rowptr, cursor, cpack, ps, pd);

    // 2-4) fused agg(L) + dense(L+1)
    fused_agg_dense<32, 64><<<NN / 16, 256>>>(W0, root[0], rbias[0], rowptr, cpack,
                                              Wr1, root[1], Ha, baseA);
    fused_agg_dense<64, 64><<<NN / 16, 256>>>(Ha, baseA, rbias[1], rowptr, cpack,
                                              Wr2, root[2], Hb, baseB);
    fused_agg_dense<64, 32><<<NN / 16, 256>>>(Hb, baseB, rbias[2], rowptr, cpack,
                                              Wr3, root[3], Ha, baseA);

    // 5) fused agg(L3) + GAT projection
    gat_h_fused<<<NN / 40, 512>>>(Ha, baseA, rbias[3], rowptr, cpack,
                                  gat_w, ps, pd, h, asv, adv);

    // 6) GAT softmax aggregation
    gat_agg_kernel<<<NN, 128>>>(h, asv, adv, rowptr, cpack, gat_b, xg);

    // 7) edge-MLP node GEMM (factorized feat@w1 = A[src]+B[dst])
    gemm_ab_kernel<<<NN / 40, 256>>>(xg, w1, ab);

    // 8) per-edge MLP tail
    edge_kernel<<<(EE * 32 + 255) / 256, 256>>>(ei, ab, b1, w2, b2, out);
}

// round 5
// speedup vs baseline: 1.0047x; 1.0047x over previous
#include <cuda_runtime.h>
#include <math.h>

#define NN 6000
#define EE 100000
#define NB 148          // persistent-kernel block count (co-resident on 148+ SMs)

typedef unsigned long long ull;

// ---------------- f32x2 packed-FMA helpers (sm_103a FFMA2) ----------------------
__device__ __forceinline__ void fma2(ull& d, ull a, ull b) {
    asm("fma.rn.f32x2 %0, %1, %2, %0;" : "+l"(d) : "l"(a), "l"(b));
}
__device__ __forceinline__ ull pack2(float lo, float hi) {
    ull r; asm("mov.b64 %0, {%1, %2};" : "=l"(r) : "f"(lo), "f"(hi)); return r;
}
__device__ __forceinline__ float2 unpack2(ull v) {
    float2 r; asm("mov.b64 {%0, %1}, %2;" : "=f"(r.x), "=f"(r.y) : "l"(v)); return r;
}

// ---------------- scratch (device globals; no allocations allowed) -------------
__device__ float g_W0[2 * NN * 32];    // layer-0 combined basis (x=I shortcut)
__device__ float g_Ha[2 * NN * 64];    // H double buffer A
__device__ float g_Hb[2 * NN * 64];    // H double buffer B
__device__ float g_baseA[NN * 64];
__device__ float g_baseB[NN * 64];
__device__ float g_Wr1[2 * 32 * 64];
__device__ float g_Wr2[2 * 64 * 64];
__device__ float g_Wr3[2 * 64 * 32];
__device__ float g_h[NN * 512];        // GAT projected features
__device__ float g_xg[NN * 512];       // GAT output
__device__ float g_ab[NN * 256];       // [A | B] for edge MLP
__device__ float g_asv[NN];
__device__ float g_adv[NN];
__device__ float g_ps[32];
__device__ float g_pd[32];
__device__ int   g_deg[NN];
__device__ int   g_rowptr[NN + 1];
__device__ int   g_cursor[NN];
__device__ int   g_cpack[EE];          // src | (type<<31)
__device__ int   g_bar_count;
__device__ int   g_bar_gen;

// ---------------- software grid barrier (all NB blocks co-resident) -------------
__device__ __forceinline__ void grid_barrier() {
    __syncthreads();
    if (threadIdx.x == 0) {
        int gen = atomicAdd(&g_bar_gen, 0);
        __threadfence();
        if (atomicAdd(&g_bar_count, 1) == NB - 1) {
            g_bar_count = 0;
            __threadfence();
            atomicAdd(&g_bar_gen, 1);
        } else {
            while (atomicAdd(&g_bar_gen, 0) == gen) __nanosleep(64);
        }
    }
    __syncthreads();
}

// ---------------- persistent: prep + count + scan + fill ------------------------
#define SEG_W0   384000
#define SEG_WR1  (SEG_W0 + 4096)
#define SEG_WR2  (SEG_WR1 + 8192)
#define SEG_WR3  (SEG_WR2 + 4096)
#define SEG_DEG  (SEG_WR3 + 6144)
#define SEG_PSPD (SEG_DEG + 2048)

__global__ __launch_bounds__(256) void csr_prep_kernel(
    const float* __restrict__ basis0, const float* __restrict__ comp0,
    const float* __restrict__ basis1, const float* __restrict__ comp1,
    const float* __restrict__ basis2, const float* __restrict__ comp2,
    const float* __restrict__ basis3, const float* __restrict__ comp3,
    const float* __restrict__ gw, const float* __restrict__ a_s,
    const float* __restrict__ a_d,
    const int* __restrict__ ei, const int* __restrict__ et,
    float* __restrict__ W0, float* __restrict__ Wr1,
    float* __restrict__ Wr2, float* __restrict__ Wr3,
    int* __restrict__ deg, int* __restrict__ rowptr, int* __restrict__ cursor,
    int* __restrict__ cpack, float* __restrict__ ps, float* __restrict__ pd) {
    const int tid = threadIdx.x;
    const int gtid = blockIdx.x * 256 + tid;
    const int gstride = NB * 256;

    // ---- phase 0: prep ----
    for (int idx = gtid; idx < SEG_PSPD; idx += gstride) {
        int i = idx;
        if (i < SEG_W0) {
            int r = i / 192000, io = i - r * 192000;
            float s = 0.f;
#pragma unroll
            for (int b = 0; b < 4; b++) s += comp0[r * 4 + b] * basis0[b * 192000 + io];
            W0[i] = s;
        } else if (i < SEG_WR1) {
            i -= SEG_W0;
            int r = i / 2048, io = i - r * 2048;
            float s = 0.f;
#pragma unroll
            for (int b = 0; b < 4; b++) s += comp1[r * 4 + b] * basis1[b * 2048 + io];
            Wr1[i] = s;
        } else if (i < SEG_WR2) {
            i -= SEG_WR1;
            int r = i / 4096, io = i - r * 4096;
            float s = 0.f;
#pragma unroll
            for (int b = 0; b < 4; b++) s += comp2[r * 4 + b] * basis2[b * 4096 + io];
            Wr2[i] = s;
        } else if (i < SEG_WR3) {
            i -= SEG_WR2;
            int r = i / 2048, io = i - r * 2048;
            float s = 0.f;
#pragma unroll
            for (int b = 0; b < 4; b++) s += comp3[r * 4 + b] * basis3[b * 2048 + io];
            Wr3[i] = s;
        } else if (i < SEG_DEG) {
            i -= SEG_WR3;
            if (i < NN) deg[i] = 0;
        } else {
            i -= SEG_DEG;
            int w = i >> 5, lane = i & 31;
            int row = w & 31;
            const float* a = (w < 32) ? a_s : a_d;
            float s = 0.f;
            for (int c = lane; c < 512; c += 32) s += gw[row * 512 + c] * a[c];
#pragma unroll
            for (int off = 16; off > 0; off >>= 1) s += __shfl_down_sync(0xffffffffu, s, off);
            if (lane == 0) { if (w < 32) ps[row] = s; else pd[row] = s; }
        }
    }
    grid_barrier();

    // ---- phase 1: count in-degrees ----
    for (int e = gtid; e < EE; e += gstride) atomicAdd(&deg[ei[EE + e]], 1);
    grid_barrier();

    // ---- phase 2: exclusive scan (block 0 only) ----
    if (blockIdx.x == 0) {
        int base = tid * 24;
        int loc[24];
        int sum = 0;
#pragma unroll
        for (int i = 0; i < 24; i++) {
            int idx = base + i;
            int v = (idx < NN) ? deg[idx] : 0;
            loc[i] = sum;
            sum += v;
        }
        int lane = tid & 31, w = tid >> 5;
        int v = sum;
#pragma unroll
        for (int off = 1; off < 32; off <<= 1) {
            int n = __shfl_up_sync(0xffffffffu, v, off);
            if (lane >= off) v += n;
        }
        __shared__ int wsum[8];
        __shared__ int stotal;
        if (lane == 31) wsum[w] = v;
        __syncthreads();
        if (tid == 0) {
            int run = 0;
#pragma unroll
            for (int j = 0; j < 8; j++) { int t = wsum[j]; wsum[j] = run; run += t; }
            stotal = run;
        }
        __syncthreads();
        int incl = v + wsum[w];
        int excl = incl - sum;
#pragma unroll
        for (int i = 0; i < 24; i++) {
            int idx = base + i;
            if (idx < NN) { rowptr[idx] = excl + loc[i]; cursor[idx] = excl + loc[i]; }
        }
        if (tid == 0) rowptr[NN] = stotal;
    }
    grid_barrier();

    // ---- phase 3: fill (packed src|type<<31) ----
    for (int e = gtid; e < EE; e += gstride) {
        int s = ei[e];
        int d = ei[EE + e];
        int t = et[e];
        int pos = atomicAdd(&cursor[d], 1);
        cpack[pos] = s | (t << 31);
    }
}

// ---------------- unroll-4 aggregation core ------------------------------------
// Walk [e0,e1) edges for one node, feature k: sum per-relation gathered rows.
template<int IN>
__device__ __forceinline__ void agg_node(const float* __restrict__ Hin,
                                         const int* __restrict__ cpack,
                                         int e0, int e1, int k,
                                         float& a0, float& a1, int& c0, int& c1) {
    int e = e0;
    for (; e + 4 <= e1; e += 4) {
        int p0 = cpack[e], p1 = cpack[e + 1], p2 = cpack[e + 2], p3 = cpack[e + 3];
        unsigned r0 = (unsigned)p0 >> 31, r1 = (unsigned)p1 >> 31;
        unsigned r2 = (unsigned)p2 >> 31, r3 = (unsigned)p3 >> 31;
        float v0 = Hin[((int)r0 * NN + (p0 & 0x7fffffff)) * IN + k];
        float v1 = Hin[((int)r1 * NN + (p1 & 0x7fffffff)) * IN + k];
        float v2 = Hin[((int)r2 * NN + (p2 & 0x7fffffff)) * IN + k];
        float v3 = Hin[((int)r3 * NN + (p3 & 0x7fffffff)) * IN + k];
        if (r0) { a1 += v0; c1++; } else { a0 += v0; c0++; }
        if (r1) { a1 += v1; c1++; } else { a0 += v1; c0++; }
        if (r2) { a1 += v2; c1++; } else { a0 += v2; c0++; }
        if (r3) { a1 += v3; c1++; } else { a0 += v3; c0++; }
    }
    for (; e < e1; e++) {
        int p = cpack[e];
        unsigned r = (unsigned)p >> 31;
        float v = Hin[((int)r * NN + (p & 0x7fffffff)) * IN + k];
        if (r) { a1 += v; c1++; } else { a0 += v; c0++; }
    }
}

// ---------------- fused agg(L) + dense(L+1) ------------------------------------
// Block: 512 threads, M=16 nodes.
template<int IN, int OUT>
__global__ __launch_bounds__(512) void fused_agg_dense(
    const float* __restrict__ Hin, const float* __restrict__ basein,
    const float* __restrict__ bias,
    const int* __restrict__ rowptr, const int* __restrict__ cpack,
    const float* __restrict__ Wr, const float* __restrict__ root,
    float* __restrict__ Hout, float* __restrict__ baseout) {
    constexpr int M = 16;
    __shared__ float xsT[IN][M];
    __shared__ float wsh[2 * IN * OUT];
    const int tid = threadIdx.x;
    const int n0 = blockIdx.x * M;

    for (int i = tid; i < 2 * IN * OUT; i += 512) wsh[i] = Wr[i];

    // phase 1: aggregate + tanh into shared (transposed), unroll-4 edge walk
    {
        const int k = tid % IN;
        const int mr = tid / IN;
        constexpr int NP = 512 / IN;
#pragma unroll
        for (int m = mr; m < M; m += NP) {
            int n = n0 + m;
            int e0 = rowptr[n], e1 = rowptr[n + 1];
            float a0 = 0.f, a1 = 0.f;
            int c0 = 0, c1 = 0;
            agg_node<IN>(Hin, cpack, e0, e1, k, a0, a1, c0, c1);
            xsT[k][m] = tanhf(basein[n * IN + k] + bias[k]
                              + a0 / fmaxf((float)c0, 1.f) + a1 / fmaxf((float)c1, 1.f));
        }
    }
    __syncthreads();

    // phase 2: dense GEMM for next layer
    constexpr int G = 512 / OUT;
    const int o = tid % OUT;
    const int g = tid / OUT;
    if constexpr (M / G == 2) {
        // pair mode (OUT=64): each thread computes nodes {2g, 2g+1} x col o
        ull a0 = 0, a1 = 0, ar = 0;
        for (int i = 0; i < IN; i++) {
            float w0 = wsh[i * OUT + o];
            float w1 = wsh[IN * OUT + i * OUT + o];
            float wr = __ldg(&root[i * OUT + o]);
            ull xp = *(const ull*)&xsT[i][2 * g];
            fma2(a0, xp, pack2(w0, w0));
            fma2(a1, xp, pack2(w1, w1));
            fma2(ar, xp, pack2(wr, wr));
        }
        int n = n0 + 2 * g;
        float2 v0 = unpack2(a0), v1 = unpack2(a1), vr = unpack2(ar);
        Hout[n * OUT + o] = v0.x;        Hout[(n + 1) * OUT + o] = v0.y;
        Hout[(NN + n) * OUT + o] = v1.x; Hout[(NN + n + 1) * OUT + o] = v1.y;
        baseout[n * OUT + o] = vr.x;     baseout[(n + 1) * OUT + o] = vr.y;
    } else {
        // scalar mode (OUT=32): one (node, col) output per thread
        float a0 = 0.f, a1 = 0.f, ar = 0.f;
        for (int i = 0; i < IN; i++) {
            float xv = xsT[i][g];
            a0 += xv * wsh[i * OUT + o];
            a1 += xv * wsh[IN * OUT + i * OUT + o];
            ar += xv * __ldg(&root[i * OUT + o]);
        }
        int n = n0 + g;
        Hout[n * OUT + o] = a0;
        Hout[(NN + n) * OUT + o] = a1;
        baseout[n * OUT + o] = ar;
    }
}

// ---------------- fused agg(L3) + GAT projection --------------------------------
__device__ __forceinline__ float lrelu02(float a) { return a > 0.f ? a : 0.2f * a; }

__global__ __launch_bounds__(512) void gat_h_fused(
    const float* __restrict__ Hin, const float* __restrict__ basein,
    const float* __restrict__ bias,
    const int* __restrict__ rowptr, const int* __restrict__ cpack,
    const float* __restrict__ gw, const float* __restrict__ ps,
    const float* __restrict__ pd,
    float* __restrict__ h, float* __restrict__ asv, float* __restrict__ adv) {
    __shared__ float xsT[32][40];
    const int c = threadIdx.x;
    const int n0 = blockIdx.x * 40;

    // phase 1: aggregate layer-3 output into shared (unroll-4 edge walk)
    {
        const int k = c & 31;
        const int mr = c >> 5;  // 16 node slots
        for (int m = mr; m < 40; m += 16) {
            int n = n0 + m;
            int e0 = rowptr[n], e1 = rowptr[n + 1];
            float a0 = 0.f, a1 = 0.f;
            int c0 = 0, c1 = 0;
            agg_node<32>(Hin, cpack, e0, e1, k, a0, a1, c0, c1);
            xsT[k][m] = tanhf(basein[n * 32 + k] + bias[k]
                              + a0 / fmaxf((float)c0, 1.f) + a1 / fmaxf((float)c1, 1.f));
        }
    }
    __syncthreads();

    // phase 2: h = x @ gw (gw column cached in registers, f32x2 node pairs)
    ull gwd[32];
#pragma unroll
    for (int k = 0; k < 32; k++) {
        float g = gw[k * 512 + c];
        gwd[k] = pack2(g, g);
    }
#pragma unroll 4
    for (int mp = 0; mp < 20; mp++) {
        ull acc = 0;
#pragma unroll
        for (int k = 0; k < 32; k++) {
            ull xp = *(const ull*)&xsT[k][2 * mp];
            fma2(acc, xp, gwd[k]);
        }
        float2 v = unpack2(acc);
        h[(size_t)(n0 + 2 * mp) * 512 + c] = v.x;
        h[(size_t)(n0 + 2 * mp + 1) * 512 + c] = v.y;
    }
    if (c < 40) {
        float s = 0.f, t = 0.f;
#pragma unroll
        for (int k = 0; k < 32; k++) {
            float xv = xsT[k][c];
            s += xv * __ldg(&ps[k]);
            t += xv * __ldg(&pd[k]);
        }
        asv[n0 + c] = s;
        adv[n0 + c] = t;
    }
}

// ---------------- GAT aggregation (softmax + weighted sum) ----------------------
__global__ void gat_agg_kernel(const float* __restrict__ h, const float* __restrict__ asv,
                               const float* __restrict__ adv,
                               const int* __restrict__ rowptr, const int* __restrict__ cpack,
                               const float* __restrict__ gbias, float* __restrict__ xout) {
    int n = blockIdx.x;
    int t = threadIdx.x;  // 128 threads, float4 per thread
    int e0 = rowptr[n], e1 = rowptr[n + 1];
    float advn = adv[n];
    float aself = lrelu02(asv[n] + advn);
    float lm = aself;
    for (int e = e0 + t; e < e1; e += 128)
        lm = fmaxf(lm, lrelu02(asv[cpack[e] & 0x7fffffff] + advn));
    __shared__ float sred[128];
    sred[t] = lm;
    __syncthreads();
    for (int off = 64; off > 0; off >>= 1) {
        if (t < off) sred[t] = fmaxf(sred[t], sred[t + off]);
        __syncthreads();
    }
    float m = sred[0];
    __shared__ float sEx[128];
    __shared__ int sSrc[128];
    float4 acc = make_float4(0.f, 0.f, 0.f, 0.f);
    float denom = 0.f;
    for (int eb = e0; eb < e1; eb += 128) {
        int cnt = min(128, e1 - eb);
        __syncthreads();
        if (t < cnt) {
            int s = cpack[eb + t] & 0x7fffffff;
            sSrc[t] = s;
            sEx[t] = expf(lrelu02(asv[s] + advn) - m);
        }
        __syncthreads();
        for (int j = 0; j < cnt; j++) {
            float ex = sEx[j];
            const float4* hr = reinterpret_cast<const float4*>(h + (size_t)sSrc[j] * 512);
            float4 v = hr[t];
            acc.x += ex * v.x; acc.y += ex * v.y; acc.z += ex * v.z; acc.w += ex * v.w;
            denom += ex;
        }
    }
    float exs = expf(aself - m);
    denom += exs;
    {
        const float4* hn = reinterpret_cast<const float4*>(h + (size_t)n * 512);
        float4 v = hn[t];
        acc.x += exs * v.x; acc.y += exs * v.y; acc.z += exs * v.z; acc.w += exs * v.w;
    }
    float inv = 1.f / fmaxf(denom, 1e-16f);
    float4 g = reinterpret_cast<const float4*>(gbias)[t];
    float4 o;
    o.x = fmaxf(acc.x * inv + g.x, 0.f);
    o.y = fmaxf(acc.y * inv + g.y, 0.f);
    o.z = fmaxf(acc.z * inv + g.z, 0.f);
    o.w = fmaxf(acc.w * inv + g.w, 0.f);
    reinterpret_cast<float4*>(xout + (size_t)n * 512)[t] = o;
}

// ---------------- edge MLP ------------------------------------------------------
__global__ __launch_bounds__(256) void gemm_ab_kernel(const float* __restrict__ xg,
                                                      const float* __restrict__ w1,
                                                      float* __restrict__ ab) {
    __shared__ float xsT[32][40];
    __shared__ float ws[32][256];
    const int c = threadIdx.x;
    const int n0 = blockIdx.x * 40;
    ull acc[20];
#pragma unroll
    for (int p = 0; p < 20; p++) acc[p] = 0;
    for (int k0 = 0; k0 < 512; k0 += 32) {
        __syncthreads();
        for (int i = c; i < 40 * 32; i += 256) {
            int m = i >> 5, kk = i & 31;
            xsT[kk][m] = xg[(size_t)(n0 + m) * 512 + k0 + kk];
        }
        for (int i = c; i < 32 * 256; i += 256) {
            int kk = i >> 8, cc = i & 255;
            int krow = k0 + kk + ((cc < 128) ? 0 : 512);
            int col = cc & 127;
            ws[kk][cc] = w1[krow * 128 + col];
        }
        __syncthreads();
#pragma unroll 8
        for (int kk = 0; kk < 32; kk++) {
            float wv = ws[kk][c];
            ull wd = pack2(wv, wv);
            const float* xr = &xsT[kk][0];
#pragma unroll
            for (int p = 0; p < 20; p++) {
                ull xp = *(const ull*)(xr + 2 * p);
                fma2(acc[p], xp, wd);
            }
        }
    }
#pragma unroll
    for (int p = 0; p < 20; p++) {
        float2 v = unpack2(acc[p]);
        ab[(size_t)(n0 + 2 * p) * 256 + c] = v.x;
        ab[(size_t)(n0 + 2 * p + 1) * 256 + c] = v.y;
    }
}

__global__ void edge_kernel(const int* __restrict__ ei, const float* __restrict__ ab,
                            const float* __restrict__ b1, const float* __restrict__ w2,
                            const float* __restrict__ b2, float* __restrict__ out) {
    int gid = blockIdx.x * blockDim.x + threadIdx.x;
    int e = gid >> 5;
    int lane = gid & 31;
    if (e >= EE) return;
    int s = ei[e];
    int d = ei[EE + e];
    float4 a = reinterpret_cast<const float4*>(ab + (size_t)s * 256)[lane];
    float4 bv = reinterpret_cast<const float4*>(ab + (size_t)d * 256 + 128)[lane];
    float4 bb = reinterpret_cast<const float4*>(b1)[lane];
    float4 wv = reinterpret_cast<const float4*>(w2)[lane];
    float acc = fmaxf(a.x + bv.x + bb.x, 0.f) * wv.x
              + fmaxf(a.y + bv.y + bb.y, 0.f) * wv.y
              + fmaxf(a.z + bv.z + bb.z, 0.f) * wv.z
              + fmaxf(a.w + bv.w + bb.w, 0.f) * wv.w;
#pragma unroll
    for (int off = 16; off > 0; off >>= 1) acc += __shfl_down_sync(0xffffffffu, acc, off);
    if (lane == 0) out[e] = 1.f / (1.f + expf(-(acc + b2[0])));
}

// ---------------- launch ---------------------------------------------------------
extern "C" void kernel_launch(void* const* d_in, const int* in_sizes, int n_in,
                              void* d_out, int out_size) {
    const float *basis[4], *comp[4], *root[4], *rbias[4];
    const float *gat_w, *att_s, *att_d, *gat_b, *w1, *b1, *w2, *b2;
    const int *ei, *et;

    if (in_sizes[0] == 2 * EE) {
        ei = (const int*)d_in[0];
        et = (const int*)d_in[1];
        int k = 2;
        for (int l = 0; l < 4; l++) {
            basis[l] = (const float*)d_in[k++];
            comp[l]  = (const float*)d_in[k++];
            root[l]  = (const float*)d_in[k++];
            rbias[l] = (const float*)d_in[k++];
        }
        gat_w = (const float*)d_in[18]; att_s = (const float*)d_in[19];
        att_d = (const float*)d_in[20]; gat_b = (const float*)d_in[21];
        w1 = (const float*)d_in[22]; b1 = (const float*)d_in[23];
        w2 = (const float*)d_in[24]; b2 = (const float*)d_in[25];
    } else if (in_sizes[0] == 4 * NN * 32) {
        int k = 0;
        for (int l = 0; l < 4; l++) {
            basis[l] = (const float*)d_in[k++];
            comp[l]  = (const float*)d_in[k++];
            root[l]  = (const float*)d_in[k++];
            rbias[l] = (const float*)d_in[k++];
        }
        gat_w = (const float*)d_in[16]; att_s = (const float*)d_in[17];
        att_d = (const float*)d_in[18]; gat_b = (const float*)d_in[19];
        w1 = (const float*)d_in[20]; b1 = (const float*)d_in[21];
        w2 = (const float*)d_in[22]; b2 = (const float*)d_in[23];
        ei = (const int*)d_in[24]; et = (const int*)d_in[25];
    } else {
        b1 = (const float*)d_in[0]; b2 = (const float*)d_in[1];
        for (int l = 0; l < 4; l++) basis[l] = (const float*)d_in[2 + l];
        for (int l = 0; l < 4; l++) comp[l] = (const float*)d_in[6 + l];
        ei = (const int*)d_in[10]; et = (const int*)d_in[11];
        att_d = (const float*)d_in[12]; att_s = (const float*)d_in[13];
        gat_b = (const float*)d_in[14]; gat_w = (const float*)d_in[15];
        for (int l = 0; l < 4; l++) rbias[l] = (const float*)d_in[16 + l];
        for (int l = 0; l < 4; l++) root[l] = (const float*)d_in[20 + l];
        w1 = (const float*)d_in[24]; w2 = (const float*)d_in[25];
    }

    float *W0, *Ha, *Hb, *baseA, *baseB, *Wr1, *Wr2, *Wr3, *h, *xg, *ab, *asv, *adv, *ps, *pd;
    int *deg, *rowptr, *cursor, *cpack;
    cudaGetSymbolAddress((void**)&W0, g_W0);
    cudaGetSymbolAddress((void**)&Ha, g_Ha);
    cudaGetSymbolAddress((void**)&Hb, g_Hb);
    cudaGetSymbolAddress((void**)&baseA, g_baseA);
    cudaGetSymbolAddress((void**)&baseB, g_baseB);
    cudaGetSymbolAddress((void**)&Wr1, g_Wr1);
    cudaGetSymbolAddress((void**)&Wr2, g_Wr2);
    cudaGetSymbolAddress((void**)&Wr3, g_Wr3);
    cudaGetSymbolAddress((void**)&h, g_h);
    cudaGetSymbolAddress((void**)&xg, g_xg);
    cudaGetSymbolAddress((void**)&ab, g_ab);
    cudaGetSymbolAddress((void**)&asv, g_asv);
    cudaGetSymbolAddress((void**)&adv, g_adv);
    cudaGetSymbolAddress((void**)&ps, g_ps);
    cudaGetSymbolAddress((void**)&pd, g_pd);
    cudaGetSymbolAddress((void**)&deg, g_deg);
    cudaGetSymbolAddress((void**)&rowptr, g_rowptr);
    cudaGetSymbolAddress((void**)&cursor, g_cursor);
    cudaGetSymbolAddress((void**)&cpack, g_cpack);

    float* out = (float*)d_out;

    // 1) persistent prep + CSR build (software grid barriers, co-resident)
    csr_prep_kernel<<<NB, 256>>>(
        basis[0], comp[0], basis[1], comp[1], basis[2], comp[2], basis[3], comp[3],
        gat_w, att_s, att_d, ei, et,
        W0, Wr1, Wr2, Wr3, deg, rowptr, cursor, cpack, ps, pd);

    // 2-4) fused agg(L) + dense(L+1)
    fused_agg_dense<32, 64><<<NN / 16, 512>>>(W0, root[0], rbias[0], rowptr, cpack,
                                              Wr1, root[1], Ha, baseA);
    fused_agg_dense<64, 64><<<NN / 16, 512>>>(Ha, baseA, rbias[1], rowptr, cpack,
                                              Wr2, root[2], Hb, baseB);
    fused_agg_dense<64, 32><<<NN / 16, 512>>>(Hb, baseB, rbias[2], rowptr, cpack,
                                              Wr3, root[3], Ha, baseA);

    // 5) fused agg(L3) + GAT projection
    gat_h_fused<<<NN / 40, 512>>>(Ha, baseA, rbias[3], rowptr, cpack,
                                  gat_w, ps, pd, h, asv, adv);

    // 6) GAT softmax aggregation
    gat_agg_kernel<<<NN, 128>>>(h, asv, adv, rowptr, cpack, gat_b, xg);

    // 7) edge-MLP node GEMM (factorized feat@w1 = A[src]+B[dst])
    gemm_ab_kernel<<<NN / 40, 256>>>(xg, w1, ab);

    // 8) per-edge MLP tail
    edge_kernel<<<(EE * 32 + 255) / 256, 256>>>(ei, ab, b1, w2, b2, out);
}